// round 12
// baseline (speedup 1.0000x reference)
#include <cuda_runtime.h>
#include <cuda_fp16.h>
#include <cstdint>

#define S_LEN 8192
#define DIM   1024
#define NH    16
#define HD    64
#define WIN   512

// Scratch (device globals: allocation-guard safe).
__device__ float  g_QKV[S_LEN * 3 * DIM];   // fused projection output (fp32)
__device__ float  g_O[S_LEN * DIM];
__device__ __half g_Q16[S_LEN * DIM];       // rope'd Q, fp16
__device__ __half g_K16[S_LEN * DIM];       // rope'd K, fp16
__device__ __half g_Vh16[S_LEN * DIM];      // V hi
__device__ __half g_Vl16[S_LEN * DIM];      // V lo
__device__ __half g_Wh[4 * DIM * DIM];      // Wq|Wk|Wv|Wo hi (contiguous)
__device__ __half g_Wl[4 * DIM * DIM];      // lo

// ===========================================================================
// helpers (legacy mma.sync path: tcgen05 gated off at PTX target sm_100)
// ===========================================================================
__device__ __forceinline__ uint32_t smem_to_u32(const void* p) {
    uint32_t a;
    asm("{ .reg .u64 t; cvta.to.shared.u64 t, %1; cvt.u32.u64 %0, t; }"
        : "=r"(a) : "l"(p));
    return a;
}
__device__ __forceinline__ void ldmx4(uint32_t* r, uint32_t addr) {
    asm volatile("ldmatrix.sync.aligned.m8n8.x4.shared.b16 {%0,%1,%2,%3}, [%4];"
        : "=r"(r[0]), "=r"(r[1]), "=r"(r[2]), "=r"(r[3]) : "r"(addr));
}
__device__ __forceinline__ void ldmx4t(uint32_t* r, uint32_t addr) {
    asm volatile("ldmatrix.sync.aligned.m8n8.x4.trans.shared.b16 {%0,%1,%2,%3}, [%4];"
        : "=r"(r[0]), "=r"(r[1]), "=r"(r[2]), "=r"(r[3]) : "r"(addr));
}
__device__ __forceinline__ void mma_f16(float* d, const uint32_t* a, const uint32_t* b) {
    asm volatile(
        "mma.sync.aligned.m16n8k16.row.col.f32.f16.f16.f32 "
        "{%0,%1,%2,%3}, {%4,%5,%6,%7}, {%8,%9}, {%0,%1,%2,%3};"
        : "+f"(d[0]), "+f"(d[1]), "+f"(d[2]), "+f"(d[3])
        : "r"(a[0]), "r"(a[1]), "r"(a[2]), "r"(a[3]), "r"(b[0]), "r"(b[1]));
}
#define SMEM_SWIZZLE_128B(byte_offset) \
    ((byte_offset) ^ (((byte_offset) >> 3) & 0x70))

__device__ __forceinline__ uint32_t pack2h(float a, float b) {
    __half2 h = __floats2half2_rn(a, b);
    return *reinterpret_cast<uint32_t*>(&h);
}
__device__ __forceinline__ void pack_split2h(float e0, float e1,
                                             uint32_t& hi, uint32_t& lo) {
    __half2 h = __floats2half2_rn(e0, e1);
    float r0 = e0 - __low2float(h);
    float r1 = e1 - __high2float(h);
    __half2 l = __floats2half2_rn(r0, r1);
    hi = *reinterpret_cast<uint32_t*>(&h);
    lo = *reinterpret_cast<uint32_t*>(&l);
}
__device__ __forceinline__ void cvt4h(float4 v, uint2& hi) {
    hi.x = pack2h(v.x, v.y);
    hi.y = pack2h(v.z, v.w);
}
__device__ __forceinline__ void split4h(float4 v, uint2& hi, uint2& lo) {
    __half2 a = __floats2half2_rn(v.x, v.y);
    __half2 b = __floats2half2_rn(v.z, v.w);
    hi.x = *reinterpret_cast<uint32_t*>(&a);
    hi.y = *reinterpret_cast<uint32_t*>(&b);
    lo.x = pack2h(v.x - __low2float(a), v.y - __high2float(a));
    lo.y = pack2h(v.z - __low2float(b), v.w - __high2float(b));
}
// fast exp2 on the FMA pipe (no MUFU)
__device__ __forceinline__ float exp2f_fast(float x) {
    x = fmaxf(x, -126.0f);
    float n = rintf(x);
    float f = x - n;
    float p = 0.00133335581f;
    p = fmaf(p, f, 0.00961812911f);
    p = fmaf(p, f, 0.05550410866f);
    p = fmaf(p, f, 0.24022650700f);
    p = fmaf(p, f, 0.69314718056f);
    p = fmaf(p, f, 1.0f);
    return p * __int_as_float(((int)n + 127) << 23);
}

// ===========================================================================
// weight split: all four fp32 weights -> contiguous (hi, lo) fp16 arrays
// ===========================================================================
#define NW (DIM * DIM)
__global__ __launch_bounds__(256) void split_all(const float* __restrict__ Wq,
                                                 const float* __restrict__ Wk,
                                                 const float* __restrict__ Wv,
                                                 const float* __restrict__ Wo)
{
    int i = blockIdx.x * blockDim.x + threadIdx.x;   // pair index, 4*NW/2 total
    int sel = i / (NW / 2);
    int off = i - sel * (NW / 2);
    const float* src = (sel == 0) ? Wq : (sel == 1) ? Wk : (sel == 2) ? Wv : Wo;
    float2 v = *(const float2*)(src + 2 * (size_t)off);
    uint32_t hi, lo;
    pack_split2h(v.x, v.y, hi, lo);
    ((uint32_t*)g_Wh)[i] = hi;
    ((uint32_t*)g_Wl)[i] = lo;
}

// ===========================================================================
// Fused QKV GEMM NT: C[8192, 3072] = x[8192,1024] * Wqkv[3072,1024]^T.
// prod=1 (fp16 rn) for Q,K columns; prod=2 (W hi+lo) for V columns.
// 128x128 tile, BK=64, 256 threads, 2-stage register-prefetch pipeline.
// ===========================================================================
#define TILE_B 16384
#define STAGE_B (4 * TILE_B)
#define GSMEM_TOTAL (2 * STAGE_B)
#define NCHUNK 16

__global__ __launch_bounds__(256) void gemm_qkv(const float* __restrict__ A)
{
    extern __shared__ __align__(1024) char smem[];
    const uint32_t sb = smem_to_u32(smem);
    const int tid  = threadIdx.x;
    const int wid  = tid >> 5;
    const int lane = tid & 31;
    const int m0   = blockIdx.y * 128;
    const int n0   = blockIdx.x * 128;           // 0..2944
    const int prod = (n0 >= 2048) ? 2 : 1;
    const int K    = DIM;
    const int wm   = wid & 1;
    const int wn   = wid >> 1;
    const __half* Bh = g_Wh;                     // row n at g_Wh + n*DIM
    const __half* Bl = g_Wl;
    float* C = g_QKV;

    const int aRow = wm * 64 + (lane & 15);
    const int aKb  = ((lane >> 4) & 1) * 16;
    const uint32_t aXor = (uint32_t)((aRow & 7) << 4);
    const int bRow = wn * 32 + (lane & 7) + ((lane >> 4) & 1) * 8;
    const int bKb  = ((lane >> 3) & 1) * 16;
    const uint32_t bXor = (uint32_t)((bRow & 7) << 4);

    float acc[4][4][4];
#pragma unroll
    for (int mt = 0; mt < 4; mt++)
#pragma unroll
        for (int nt = 0; nt < 4; nt++)
#pragma unroll
            for (int q = 0; q < 4; q++) acc[mt][nt][q] = 0.f;

    // ---- prologue: stage chunk 0 ----
    {
        char* st = smem;
#pragma unroll
        for (int it = 0; it < 8; it++) {
            int f = tid + (it << 8);
            int row = f >> 4;
            int cg  = (f & 15) << 2;
            uint32_t off = SMEM_SWIZZLE_128B((uint32_t)(row * 128 + cg * 2));
            float4 va = *(const float4*)(A + (size_t)(m0 + row) * K + cg);
            uint2 h;
            cvt4h(va, h);
            *(uint2*)(st + off) = h;
        }
#pragma unroll
        for (int i = 0; i < 4; i++) {
            int idx = tid * 4 + i;
            int row = idx >> 3;
            int c16 = idx & 7;
            uint32_t off = SMEM_SWIZZLE_128B((uint32_t)(row * 128 + c16 * 16));
            *(uint4*)(st + 2 * TILE_B + off) =
                *(const uint4*)(Bh + (size_t)(n0 + row) * K + c16 * 8);
            if (prod >= 2)
                *(uint4*)(st + 3 * TILE_B + off) =
                    *(const uint4*)(Bl + (size_t)(n0 + row) * K + c16 * 8);
        }
    }
    __syncthreads();

    for (int c = 0; c < NCHUNK; c++) {
        const int buf = c & 1;
        const uint32_t sAh = sb + buf * STAGE_B;
        const uint32_t sBh = sAh + 2 * TILE_B;
        const uint32_t sBl = sAh + 3 * TILE_B;

        float4 ra[8];
        uint4  rbh[4], rbl[4];
        if (c + 1 < NCHUNK) {
            const float* Ap = A + (size_t)m0 * K + (c + 1) * 64;
#pragma unroll
            for (int it = 0; it < 8; it++) {
                int f = tid + (it << 8);
                int row = f >> 4;
                int cg  = (f & 15) << 2;
                ra[it] = *(const float4*)(Ap + (size_t)row * K + cg);
            }
            const __half* Bhp = Bh + (size_t)n0 * K + (c + 1) * 64;
            const __half* Blp = Bl + (size_t)n0 * K + (c + 1) * 64;
#pragma unroll
            for (int i = 0; i < 4; i++) {
                int idx = tid * 4 + i;
                int row = idx >> 3;
                int c16 = idx & 7;
                rbh[i] = *(const uint4*)(Bhp + (size_t)row * K + c16 * 8);
                if (prod >= 2)
                    rbl[i] = *(const uint4*)(Blp + (size_t)row * K + c16 * 8);
            }
        }

#pragma unroll
        for (int ks = 0; ks < 4; ks++) {
            uint32_t ah[4][4], bh[4][2], bl[4][2];
#pragma unroll
            for (int mt = 0; mt < 4; mt++) {
                uint32_t off = (uint32_t)((aRow + mt * 16) * 128) +
                               (((uint32_t)(ks * 32 + aKb)) ^ aXor);
                ldmx4(ah[mt], sAh + off);
            }
#pragma unroll
            for (int np = 0; np < 2; np++) {
                uint32_t off = (uint32_t)((bRow + np * 16) * 128) +
                               (((uint32_t)(ks * 32 + bKb)) ^ bXor);
                uint32_t r[4];
                ldmx4(r, sBh + off);
                bh[2*np][0] = r[0]; bh[2*np][1] = r[1];
                bh[2*np+1][0] = r[2]; bh[2*np+1][1] = r[3];
                if (prod >= 2) {
                    ldmx4(r, sBl + off);
                    bl[2*np][0] = r[0]; bl[2*np][1] = r[1];
                    bl[2*np+1][0] = r[2]; bl[2*np+1][1] = r[3];
                }
            }
#pragma unroll
            for (int mt = 0; mt < 4; mt++)
#pragma unroll
                for (int nt = 0; nt < 4; nt++) {
                    mma_f16(acc[mt][nt], ah[mt], bh[nt]);
                    if (prod >= 2) mma_f16(acc[mt][nt], ah[mt], bl[nt]);
                }
        }

        if (c + 1 < NCHUNK) {
            char* st = smem + (buf ^ 1) * STAGE_B;
#pragma unroll
            for (int it = 0; it < 8; it++) {
                int f = tid + (it << 8);
                int row = f >> 4;
                int cg  = (f & 15) << 2;
                uint32_t off = SMEM_SWIZZLE_128B((uint32_t)(row * 128 + cg * 2));
                uint2 h;
                cvt4h(ra[it], h);
                *(uint2*)(st + off) = h;
            }
#pragma unroll
            for (int i = 0; i < 4; i++) {
                int idx = tid * 4 + i;
                int row = idx >> 3;
                int c16 = idx & 7;
                uint32_t off = SMEM_SWIZZLE_128B((uint32_t)(row * 128 + c16 * 16));
                *(uint4*)(st + 2 * TILE_B + off) = rbh[i];
                if (prod >= 2) *(uint4*)(st + 3 * TILE_B + off) = rbl[i];
            }
        }
        __syncthreads();
    }

#pragma unroll
    for (int mt = 0; mt < 4; mt++) {
        int r0 = m0 + wm * 64 + mt * 16 + (lane >> 2);
#pragma unroll
        for (int nt = 0; nt < 4; nt++) {
            int c0 = n0 + wn * 32 + nt * 8 + (lane & 3) * 2;
            *(float2*)(C + (size_t)r0 * 3072 + c0) =
                make_float2(acc[mt][nt][0], acc[mt][nt][1]);
            *(float2*)(C + (size_t)(r0 + 8) * 3072 + c0) =
                make_float2(acc[mt][nt][2], acc[mt][nt][3]);
        }
    }
}

// ===========================================================================
// Wo GEMM (PROD=3): out = O * Wo^T, O fp32 split in-kernel, Wo pre-split.
// ===========================================================================
__global__ __launch_bounds__(256) void gemm_out(const float* __restrict__ A,
                                                float* __restrict__ C)
{
    extern __shared__ __align__(1024) char smem[];
    const uint32_t sb = smem_to_u32(smem);
    const int tid  = threadIdx.x;
    const int wid  = tid >> 5;
    const int lane = tid & 31;
    const int m0   = blockIdx.y * 128;
    const int n0   = blockIdx.x * 128;
    const int wm   = wid & 1;
    const int wn   = wid >> 1;
    const int K    = DIM;
    const __half* Bh = g_Wh + 3 * (size_t)NW;
    const __half* Bl = g_Wl + 3 * (size_t)NW;

    const int aRow = wm * 64 + (lane & 15);
    const int aKb  = ((lane >> 4) & 1) * 16;
    const uint32_t aXor = (uint32_t)((aRow & 7) << 4);
    const int bRow = wn * 32 + (lane & 7) + ((lane >> 4) & 1) * 8;
    const int bKb  = ((lane >> 3) & 1) * 16;
    const uint32_t bXor = (uint32_t)((bRow & 7) << 4);

    float acc[4][4][4];
#pragma unroll
    for (int mt = 0; mt < 4; mt++)
#pragma unroll
        for (int nt = 0; nt < 4; nt++)
#pragma unroll
            for (int q = 0; q < 4; q++) acc[mt][nt][q] = 0.f;

    {
        char* st = smem;
#pragma unroll
        for (int it = 0; it < 8; it++) {
            int f = tid + (it << 8);
            int row = f >> 4;
            int cg  = (f & 15) << 2;
            uint32_t off = SMEM_SWIZZLE_128B((uint32_t)(row * 128 + cg * 2));
            float4 va = *(const float4*)(A + (size_t)(m0 + row) * K + cg);
            uint2 h, l;
            split4h(va, h, l);
            *(uint2*)(st + off)          = h;
            *(uint2*)(st + TILE_B + off) = l;
        }
#pragma unroll
        for (int i = 0; i < 4; i++) {
            int idx = tid * 4 + i;
            int row = idx >> 3;
            int c16 = idx & 7;
            uint32_t off = SMEM_SWIZZLE_128B((uint32_t)(row * 128 + c16 * 16));
            *(uint4*)(st + 2 * TILE_B + off) =
                *(const uint4*)(Bh + (size_t)(n0 + row) * K + c16 * 8);
            *(uint4*)(st + 3 * TILE_B + off) =
                *(const uint4*)(Bl + (size_t)(n0 + row) * K + c16 * 8);
        }
    }
    __syncthreads();

    for (int c = 0; c < NCHUNK; c++) {
        const int buf = c & 1;
        const uint32_t sAh = sb + buf * STAGE_B;
        const uint32_t sAl = sAh + TILE_B;
        const uint32_t sBh = sAh + 2 * TILE_B;
        const uint32_t sBl = sAh + 3 * TILE_B;

        float4 ra[8];
        uint4  rbh[4], rbl[4];
        if (c + 1 < NCHUNK) {
            const float* Ap = A + (size_t)m0 * K + (c + 1) * 64;
#pragma unroll
            for (int it = 0; it < 8; it++) {
                int f = tid + (it << 8);
                int row = f >> 4;
                int cg  = (f & 15) << 2;
                ra[it] = *(const float4*)(Ap + (size_t)row * K + cg);
            }
            const __half* Bhp = Bh + (size_t)n0 * K + (c + 1) * 64;
            const __half* Blp = Bl + (size_t)n0 * K + (c + 1) * 64;
#pragma unroll
            for (int i = 0; i < 4; i++) {
                int idx = tid * 4 + i;
                int row = idx >> 3;
                int c16 = idx & 7;
                rbh[i] = *(const uint4*)(Bhp + (size_t)row * K + c16 * 8);
                rbl[i] = *(const uint4*)(Blp + (size_t)row * K + c16 * 8);
            }
        }

#pragma unroll
        for (int ks = 0; ks < 4; ks++) {
            uint32_t ah[4][4], al[4][4], bh[4][2], bl[4][2];
#pragma unroll
            for (int mt = 0; mt < 4; mt++) {
                uint32_t off = (uint32_t)((aRow + mt * 16) * 128) +
                               (((uint32_t)(ks * 32 + aKb)) ^ aXor);
                ldmx4(ah[mt], sAh + off);
                ldmx4(al[mt], sAl + off);
            }
#pragma unroll
            for (int np = 0; np < 2; np++) {
                uint32_t off = (uint32_t)((bRow + np * 16) * 128) +
                               (((uint32_t)(ks * 32 + bKb)) ^ bXor);
                uint32_t r[4];
                ldmx4(r, sBh + off);
                bh[2*np][0] = r[0]; bh[2*np][1] = r[1];
                bh[2*np+1][0] = r[2]; bh[2*np+1][1] = r[3];
                ldmx4(r, sBl + off);
                bl[2*np][0] = r[0]; bl[2*np][1] = r[1];
                bl[2*np+1][0] = r[2]; bl[2*np+1][1] = r[3];
            }
#pragma unroll
            for (int mt = 0; mt < 4; mt++)
#pragma unroll
                for (int nt = 0; nt < 4; nt++) {
                    mma_f16(acc[mt][nt], ah[mt], bh[nt]);
                    mma_f16(acc[mt][nt], ah[mt], bl[nt]);
                    mma_f16(acc[mt][nt], al[mt], bh[nt]);
                }
        }

        if (c + 1 < NCHUNK) {
            char* st = smem + (buf ^ 1) * STAGE_B;
#pragma unroll
            for (int it = 0; it < 8; it++) {
                int f = tid + (it << 8);
                int row = f >> 4;
                int cg  = (f & 15) << 2;
                uint32_t off = SMEM_SWIZZLE_128B((uint32_t)(row * 128 + cg * 2));
                uint2 h, l;
                split4h(ra[it], h, l);
                *(uint2*)(st + off)          = h;
                *(uint2*)(st + TILE_B + off) = l;
            }
#pragma unroll
            for (int i = 0; i < 4; i++) {
                int idx = tid * 4 + i;
                int row = idx >> 3;
                int c16 = idx & 7;
                uint32_t off = SMEM_SWIZZLE_128B((uint32_t)(row * 128 + c16 * 16));
                *(uint4*)(st + 2 * TILE_B + off) = rbh[i];
                *(uint4*)(st + 3 * TILE_B + off) = rbl[i];
            }
        }
        __syncthreads();
    }

#pragma unroll
    for (int mt = 0; mt < 4; mt++) {
        int r0 = m0 + wm * 64 + mt * 16 + (lane >> 2);
#pragma unroll
        for (int nt = 0; nt < 4; nt++) {
            int c0 = n0 + wn * 32 + nt * 8 + (lane & 3) * 2;
            *(float2*)(C + (size_t)r0 * DIM + c0) =
                make_float2(acc[mt][nt][0], acc[mt][nt][1]);
            *(float2*)(C + (size_t)(r0 + 8) * DIM + c0) =
                make_float2(acc[mt][nt][2], acc[mt][nt][3]);
        }
    }
}

// ===========================================================================
// rope + convert: g_QKV fp32 -> rope'd fp16 Q,K + split fp16 V.
// one thread per fp32 pair; 1536 pairs per row.
// ===========================================================================
__global__ __launch_bounds__(256) void rope_cvt()
{
    int idx = blockIdx.x * blockDim.x + threadIdx.x;    // S_LEN * 1536
    int s  = idx / 1536;
    int pp = idx - s * 1536;
    float2 v = *(const float2*)(g_QKV + (size_t)s * 3072 + 2 * pp);

    if (pp < 1024) {
        int p = pp & 511;
        int i = p & 31;
        float e   = (float)(-(double)(2 * i) * 13.287712379549449 / 64.0);
        float inv = exp2f(e);
        float ang = (float)s * inv;
        float sn, cs;
        sincosf(ang, &sn, &cs);
        float a = v.x * cs - v.y * sn;
        float b = v.x * sn + v.y * cs;
        uint32_t h = pack2h(a, b);
        if (pp < 512) ((uint32_t*)g_Q16)[(size_t)s * 512 + p] = h;
        else          ((uint32_t*)g_K16)[(size_t)s * 512 + p] = h;
    } else {
        int p = pp - 1024;
        uint32_t hi, lo;
        pack_split2h(v.x, v.y, hi, lo);
        ((uint32_t*)g_Vh16)[(size_t)s * 512 + p] = hi;
        ((uint32_t*)g_Vl16)[(size_t)s * 512 + p] = lo;
    }
}

// ===========================================================================
// Sliding-window attention: QK 1-product fp16, PV 3-product fp16 split.
// All operands pre-converted fp16 — raw copies into smem, no conversion.
// CTA = (128 q, 1 head), 8 warps. smem: Q 16K | K 8K | Vh 8K | Vl 8K = 40KB.
// ===========================================================================
#define ASMEM_TOTAL 40960
#define OFF_Q  0
#define OFF_K  16384
#define OFF_VH 24576
#define OFF_VL 32768

__global__ __launch_bounds__(256) void swa_mma()
{
    extern __shared__ __align__(1024) char smem[];
    const uint32_t sb = smem_to_u32(smem);
    const int h   = blockIdx.y;
    const int q0  = blockIdx.x * 128;
    const int tid = threadIdx.x;
    const int w   = tid >> 5;
    const int lane = tid & 31;

    // ---- stage Q tile (raw fp16 copy) ----
#pragma unroll
    for (int i = 0; i < 4; i++) {
        int idx = tid * 4 + i;
        int row = idx >> 3;
        int c16 = idx & 7;
        uint32_t off = SMEM_SWIZZLE_128B((uint32_t)(row * 128 + c16 * 16));
        *(uint4*)(smem + OFF_Q + off) =
            *(const uint4*)(g_Q16 + (size_t)(q0 + row) * DIM + h * HD + c16 * 8);
    }
    __syncthreads();

    // ---- preload Q fragments ----
    uint32_t qh[4][4];
    {
        const int aRow = w * 16 + (lane & 15);
        const uint32_t aSw = (uint32_t)((aRow & 7) << 4);
#pragma unroll
        for (int ks = 0; ks < 4; ks++) {
            uint32_t off = (uint32_t)(aRow * 128) +
                           (((uint32_t)(ks * 32 + ((lane >> 4) & 1) * 16)) ^ aSw);
            ldmx4(qh[ks], sb + OFF_Q + off);
        }
    }

    const int bRow = (lane & 7) + ((lane >> 4) & 1) * 8;
    const int bKb  = ((lane >> 3) & 1) * 16;
    const uint32_t bSw = (uint32_t)((bRow & 7) << 4);
    const int vRow = (lane & 7) + ((lane >> 3) & 1) * 8;
    const int vCb  = ((lane >> 4) & 1) * 16;
    const uint32_t vSw = (uint32_t)((vRow & 7) << 4);

    float m0 = -1e30f, m1 = -1e30f, l0 = 0.f, l1 = 0.f;
    float oacc[8][4];
#pragma unroll
    for (int j = 0; j < 8; j++)
#pragma unroll
        for (int q = 0; q < 4; q++) oacc[j][q] = 0.f;

    const int kt_begin = (q0 >= WIN) ? ((q0 - WIN + 1) >> 6) : 0;
    const int kt_end   = (q0 + 127) >> 6;
    const float sc = 0.125f * 1.4426950408889634f;

    // ---- stage first K/V tile (raw fp16 copies) ----
    {
        const int k0 = kt_begin << 6;
#pragma unroll
        for (int i = 0; i < 2; i++) {
            int idx = tid * 2 + i;
            int row = idx >> 3;
            int c16 = idx & 7;
            uint32_t off = SMEM_SWIZZLE_128B((uint32_t)(row * 128 + c16 * 16));
            size_t g = (size_t)(k0 + row) * DIM + h * HD + c16 * 8;
            *(uint4*)(smem + OFF_K  + off) = *(const uint4*)(g_K16  + g);
            *(uint4*)(smem + OFF_VH + off) = *(const uint4*)(g_Vh16 + g);
            *(uint4*)(smem + OFF_VL + off) = *(const uint4*)(g_Vl16 + g);
        }
    }
    __syncthreads();

    const int qg0 = q0 + w * 16 + (lane >> 2);
    const int qg1 = qg0 + 8;

    for (int kt = kt_begin; kt <= kt_end; kt++) {
        const int k0 = kt << 6;

        // prefetch next tile into registers
        uint4 rk[2], rvh[2], rvl[2];
        if (kt < kt_end) {
            const int kn = (kt + 1) << 6;
#pragma unroll
            for (int i = 0; i < 2; i++) {
                int idx = tid * 2 + i;
                int row = idx >> 3;
                int c16 = idx & 7;
                size_t g = (size_t)(kn + row) * DIM + h * HD + c16 * 8;
                rk[i]  = *(const uint4*)(g_K16  + g);
                rvh[i] = *(const uint4*)(g_Vh16 + g);
                rvl[i] = *(const uint4*)(g_Vl16 + g);
            }
        }

        // ---- scores: 1-product fp16 QK ----
        float sacc[8][4];
#pragma unroll
        for (int j = 0; j < 8; j++)
#pragma unroll
            for (int q = 0; q < 4; q++) sacc[j][q] = 0.f;

#pragma unroll
        for (int ks = 0; ks < 4; ks++) {
#pragma unroll
            for (int np = 0; np < 4; np++) {
                uint32_t off = (uint32_t)((np * 16 + bRow) * 128) +
                               (((uint32_t)(ks * 32 + bKb)) ^ bSw);
                uint32_t kh4[4];
                ldmx4(kh4, sb + OFF_K + off);
                mma_f16(sacc[2*np],   qh[ks], kh4);
                mma_f16(sacc[2*np+1], qh[ks], kh4 + 2);
            }
        }

        // ---- mask + scale ----
#pragma unroll
        for (int j = 0; j < 8; j++) {
            int kg = k0 + 8 * j + ((lane & 3) << 1);
            sacc[j][0] = (kg   <= qg0 && kg   + WIN > qg0) ? sacc[j][0] * sc : -1e30f;
            sacc[j][1] = (kg+1 <= qg0 && kg+1 + WIN > qg0) ? sacc[j][1] * sc : -1e30f;
            sacc[j][2] = (kg   <= qg1 && kg   + WIN > qg1) ? sacc[j][2] * sc : -1e30f;
            sacc[j][3] = (kg+1 <= qg1 && kg+1 + WIN > qg1) ? sacc[j][3] * sc : -1e30f;
        }

        // ---- online softmax ----
        float t0 = -1e30f, t1 = -1e30f;
#pragma unroll
        for (int j = 0; j < 8; j++) {
            t0 = fmaxf(t0, fmaxf(sacc[j][0], sacc[j][1]));
            t1 = fmaxf(t1, fmaxf(sacc[j][2], sacc[j][3]));
        }
        t0 = fmaxf(t0, __shfl_xor_sync(0xffffffffu, t0, 1));
        t0 = fmaxf(t0, __shfl_xor_sync(0xffffffffu, t0, 2));
        t1 = fmaxf(t1, __shfl_xor_sync(0xffffffffu, t1, 1));
        t1 = fmaxf(t1, __shfl_xor_sync(0xffffffffu, t1, 2));
        float mn0 = fmaxf(m0, t0), mn1 = fmaxf(m1, t1);
        float c0 = exp2f_fast(m0 - mn0), c1 = exp2f_fast(m1 - mn1);
        m0 = mn0; m1 = mn1;

        float s0 = 0.f, s1 = 0.f;
#pragma unroll
        for (int j = 0; j < 8; j++) {
            float p0 = exp2f_fast(sacc[j][0] - m0);
            float p1 = exp2f_fast(sacc[j][1] - m0);
            float p2 = exp2f_fast(sacc[j][2] - m1);
            float p3 = exp2f_fast(sacc[j][3] - m1);
            sacc[j][0] = p0; sacc[j][1] = p1; sacc[j][2] = p2; sacc[j][3] = p3;
            s0 += p0 + p1; s1 += p2 + p3;
        }
        s0 += __shfl_xor_sync(0xffffffffu, s0, 1);
        s0 += __shfl_xor_sync(0xffffffffu, s0, 2);
        s1 += __shfl_xor_sync(0xffffffffu, s1, 1);
        s1 += __shfl_xor_sync(0xffffffffu, s1, 2);
        l0 = l0 * c0 + s0;
        l1 = l1 * c1 + s1;
#pragma unroll
        for (int j = 0; j < 8; j++) {
            oacc[j][0] *= c0; oacc[j][1] *= c0;
            oacc[j][2] *= c1; oacc[j][3] *= c1;
        }

        // ---- pack P (fp16 hi/lo) ----
        uint32_t aPh[4][4], aPl[4][4];
#pragma unroll
        for (int t = 0; t < 4; t++) {
            pack_split2h(sacc[2*t][0],   sacc[2*t][1],   aPh[t][0], aPl[t][0]);
            pack_split2h(sacc[2*t][2],   sacc[2*t][3],   aPh[t][1], aPl[t][1]);
            pack_split2h(sacc[2*t+1][0], sacc[2*t+1][1], aPh[t][2], aPl[t][2]);
            pack_split2h(sacc[2*t+1][2], sacc[2*t+1][3], aPh[t][3], aPl[t][3]);
        }

        // ---- O += P V (3-product fp16) ----
#pragma unroll
        for (int t = 0; t < 4; t++) {
#pragma unroll
            for (int j2 = 0; j2 < 4; j2++) {
                uint32_t off = (uint32_t)((t * 16 + vRow) * 128) +
                               (((uint32_t)(j2 * 32 + vCb)) ^ vSw);
                uint32_t vh4[4], vl4[4];
                ldmx4t(vh4, sb + OFF_VH + off);
                ldmx4t(vl4, sb + OFF_VL + off);
                mma_f16(oacc[2*j2],   aPh[t], vh4);
                mma_f16(oacc[2*j2],   aPh[t], vl4);
                mma_f16(oacc[2*j2],   aPl[t], vh4);
                mma_f16(oacc[2*j2+1], aPh[t], vh4 + 2);
                mma_f16(oacc[2*j2+1], aPh[t], vl4 + 2);
                mma_f16(oacc[2*j2+1], aPl[t], vh4 + 2);
            }
        }

        __syncthreads();
        if (kt < kt_end) {
#pragma unroll
            for (int i = 0; i < 2; i++) {
                int idx = tid * 2 + i;
                int row = idx >> 3;
                int c16 = idx & 7;
                uint32_t off = SMEM_SWIZZLE_128B((uint32_t)(row * 128 + c16 * 16));
                *(uint4*)(smem + OFF_K  + off) = rk[i];
                *(uint4*)(smem + OFF_VH + off) = rvh[i];
                *(uint4*)(smem + OFF_VL + off) = rvl[i];
            }
            __syncthreads();
        }
    }

    // ---- epilogue: O /= l ----
    float inv0 = 1.f / l0, inv1 = 1.f / l1;
    const int r0g = q0 + w * 16 + (lane >> 2);
#pragma unroll
    for (int j = 0; j < 8; j++) {
        int c0 = h * HD + 8 * j + ((lane & 3) << 1);
        *(float2*)(g_O + (size_t)r0g * DIM + c0) =
            make_float2(oacc[j][0] * inv0, oacc[j][1] * inv0);
        *(float2*)(g_O + (size_t)(r0g + 8) * DIM + c0) =
            make_float2(oacc[j][2] * inv1, oacc[j][3] * inv1);
    }
}

// ---------------------------------------------------------------------------
extern "C" void kernel_launch(void* const* d_in, const int* in_sizes, int n_in,
                              void* d_out, int out_size)
{
    const float* x  = (const float*)d_in[0];
    const float* Wq = (const float*)d_in[1];
    const float* Wk = (const float*)d_in[2];
    const float* Wv = (const float*)d_in[3];
    const float* Wo = (const float*)d_in[4];
    float* out = (float*)d_out;
    (void)in_sizes; (void)n_in; (void)out_size;

    static float* pO = nullptr;
    static bool init_done = false;
    if (!init_done) {
        cudaGetSymbolAddress((void**)&pO, g_O);
        cudaFuncSetAttribute(gemm_qkv, cudaFuncAttributeMaxDynamicSharedMemorySize,
                             GSMEM_TOTAL);
        cudaFuncSetAttribute(gemm_out, cudaFuncAttributeMaxDynamicSharedMemorySize,
                             GSMEM_TOTAL);
        cudaFuncSetAttribute(swa_mma, cudaFuncAttributeMaxDynamicSharedMemorySize,
                             ASMEM_TOTAL);
        init_done = true;
    }

    // split all 4 weights into contiguous fp16 hi/lo
    split_all<<<(4 * NW / 2) / 256, 256>>>(Wq, Wk, Wv, Wo);

    // fused QKV projection (Q,K: 1 product; V: 2 products)
    gemm_qkv<<<dim3(3 * DIM / 128, S_LEN / 128), 256, GSMEM_TOTAL>>>(x);

    // rope + fp16 conversion/split
    rope_cvt<<<(S_LEN * 1536) / 256, 256>>>();

    // attention
    swa_mma<<<dim3(S_LEN / 128, NH), 256, ASMEM_TOTAL>>>();

    // output projection (3 products)
    gemm_out<<<dim3(DIM / 128, S_LEN / 128), 256, GSMEM_TOTAL>>>(pO, out);
}

// round 13
// speedup vs baseline: 1.0586x; 1.0586x over previous
#include <cuda_runtime.h>
#include <cuda_fp16.h>
#include <cstdint>

#define S_LEN 8192
#define DIM   1024
#define NH    16
#define HD    64
#define WIN   512

// Scratch (device globals: allocation-guard safe).
__device__ float  g_Q[S_LEN * DIM];
__device__ float  g_K[S_LEN * DIM];
__device__ float  g_V[S_LEN * DIM];
__device__ float  g_O[S_LEN * DIM];
__device__ __half g_Q16[S_LEN * DIM];
__device__ __half g_K16[S_LEN * DIM];
__device__ __half g_Vh16[S_LEN * DIM];
__device__ __half g_Vl16[S_LEN * DIM];
__device__ __half g_Wh[4 * DIM * DIM];
__device__ __half g_Wl[4 * DIM * DIM];

// ===========================================================================
// helpers (legacy mma.sync path: tcgen05 gated off at PTX target sm_100)
// ===========================================================================
__device__ __forceinline__ uint32_t smem_to_u32(const void* p) {
    uint32_t a;
    asm("{ .reg .u64 t; cvta.to.shared.u64 t, %1; cvt.u32.u64 %0, t; }"
        : "=r"(a) : "l"(p));
    return a;
}
__device__ __forceinline__ void ldmx4(uint32_t* r, uint32_t addr) {
    asm volatile("ldmatrix.sync.aligned.m8n8.x4.shared.b16 {%0,%1,%2,%3}, [%4];"
        : "=r"(r[0]), "=r"(r[1]), "=r"(r[2]), "=r"(r[3]) : "r"(addr));
}
__device__ __forceinline__ void ldmx4t(uint32_t* r, uint32_t addr) {
    asm volatile("ldmatrix.sync.aligned.m8n8.x4.trans.shared.b16 {%0,%1,%2,%3}, [%4];"
        : "=r"(r[0]), "=r"(r[1]), "=r"(r[2]), "=r"(r[3]) : "r"(addr));
}
__device__ __forceinline__ void mma_f16(float* d, const uint32_t* a, const uint32_t* b) {
    asm volatile(
        "mma.sync.aligned.m16n8k16.row.col.f32.f16.f16.f32 "
        "{%0,%1,%2,%3}, {%4,%5,%6,%7}, {%8,%9}, {%0,%1,%2,%3};"
        : "+f"(d[0]), "+f"(d[1]), "+f"(d[2]), "+f"(d[3])
        : "r"(a[0]), "r"(a[1]), "r"(a[2]), "r"(a[3]), "r"(b[0]), "r"(b[1]));
}
#define SMEM_SWIZZLE_128B(byte_offset) \
    ((byte_offset) ^ (((byte_offset) >> 3) & 0x70))

__device__ __forceinline__ uint32_t pack2h(float a, float b) {
    __half2 h = __floats2half2_rn(a, b);
    return *reinterpret_cast<uint32_t*>(&h);
}
__device__ __forceinline__ void pack_split2h(float e0, float e1,
                                             uint32_t& hi, uint32_t& lo) {
    __half2 h = __floats2half2_rn(e0, e1);
    float r0 = e0 - __low2float(h);
    float r1 = e1 - __high2float(h);
    __half2 l = __floats2half2_rn(r0, r1);
    hi = *reinterpret_cast<uint32_t*>(&h);
    lo = *reinterpret_cast<uint32_t*>(&l);
}
__device__ __forceinline__ void cvt4h(float4 v, uint2& hi) {
    hi.x = pack2h(v.x, v.y);
    hi.y = pack2h(v.z, v.w);
}
__device__ __forceinline__ void split4h(float4 v, uint2& hi, uint2& lo) {
    __half2 a = __floats2half2_rn(v.x, v.y);
    __half2 b = __floats2half2_rn(v.z, v.w);
    hi.x = *reinterpret_cast<uint32_t*>(&a);
    hi.y = *reinterpret_cast<uint32_t*>(&b);
    lo.x = pack2h(v.x - __low2float(a), v.y - __high2float(a));
    lo.y = pack2h(v.z - __low2float(b), v.w - __high2float(b));
}
// fast exp2 on the FMA pipe (no MUFU)
__device__ __forceinline__ float exp2f_fast(float x) {
    x = fmaxf(x, -126.0f);
    float n = rintf(x);
    float f = x - n;
    float p = 0.00133335581f;
    p = fmaf(p, f, 0.00961812911f);
    p = fmaf(p, f, 0.05550410866f);
    p = fmaf(p, f, 0.24022650700f);
    p = fmaf(p, f, 0.69314718056f);
    p = fmaf(p, f, 1.0f);
    return p * __int_as_float(((int)n + 127) << 23);
}

// ===========================================================================
// weight split: all four fp32 weights -> contiguous (hi, lo) fp16 arrays
// ===========================================================================
#define NW (DIM * DIM)
__global__ __launch_bounds__(256) void split_all(const float* __restrict__ Wq,
                                                 const float* __restrict__ Wk,
                                                 const float* __restrict__ Wv,
                                                 const float* __restrict__ Wo)
{
    int i = blockIdx.x * blockDim.x + threadIdx.x;
    int sel = i / (NW / 2);
    int off = i - sel * (NW / 2);
    const float* src = (sel == 0) ? Wq : (sel == 1) ? Wk : (sel == 2) ? Wv : Wo;
    float2 v = *(const float2*)(src + 2 * (size_t)off);
    uint32_t hi, lo;
    pack_split2h(v.x, v.y, hi, lo);
    ((uint32_t*)g_Wh)[i] = hi;
    ((uint32_t*)g_Wl)[i] = lo;
}

// ===========================================================================
// GEMM NT, PROD products (R11 verbatim): C = A * B^T.
//  PROD=1: Ah*Bh ; PROD=2: Ah*(Bh+Bl) ; PROD=3: (Ah+Al)*Bh + Ah*Bl
// ===========================================================================
#define TILE_B 16384
#define STAGE_B (4 * TILE_B)
#define GSMEM_TOTAL (2 * STAGE_B)
#define NCHUNK 16

template<int PROD>
__global__ __launch_bounds__(256) void gemm_f16(const float* __restrict__ A,
                                                const __half* __restrict__ Bh,
                                                const __half* __restrict__ Bl,
                                                float* __restrict__ C)
{
    extern __shared__ __align__(1024) char smem[];
    const uint32_t sb = smem_to_u32(smem);
    const int tid  = threadIdx.x;
    const int wid  = tid >> 5;
    const int lane = tid & 31;
    const int m0   = blockIdx.y * 128;
    const int n0   = blockIdx.x * 128;
    const int wm   = wid & 1;
    const int wn   = wid >> 1;
    const int K    = DIM;

    const int aRow = wm * 64 + (lane & 15);
    const int aKb  = ((lane >> 4) & 1) * 16;
    const uint32_t aXor = (uint32_t)((aRow & 7) << 4);
    const int bRow = wn * 32 + (lane & 7) + ((lane >> 4) & 1) * 8;
    const int bKb  = ((lane >> 3) & 1) * 16;
    const uint32_t bXor = (uint32_t)((bRow & 7) << 4);

    float acc[4][4][4];
#pragma unroll
    for (int mt = 0; mt < 4; mt++)
#pragma unroll
        for (int nt = 0; nt < 4; nt++)
#pragma unroll
            for (int q = 0; q < 4; q++) acc[mt][nt][q] = 0.f;

    {
        char* st = smem;
#pragma unroll
        for (int it = 0; it < 8; it++) {
            int f = tid + (it << 8);
            int row = f >> 4;
            int cg  = (f & 15) << 2;
            uint32_t off = SMEM_SWIZZLE_128B((uint32_t)(row * 128 + cg * 2));
            float4 va = *(const float4*)(A + (size_t)(m0 + row) * K + cg);
            uint2 h, l;
            if (PROD == 3) { split4h(va, h, l); *(uint2*)(st + TILE_B + off) = l; }
            else           { cvt4h(va, h); }
            *(uint2*)(st + off) = h;
        }
#pragma unroll
        for (int i = 0; i < 4; i++) {
            int idx = tid * 4 + i;
            int row = idx >> 3;
            int c16 = idx & 7;
            uint32_t off = SMEM_SWIZZLE_128B((uint32_t)(row * 128 + c16 * 16));
            *(uint4*)(st + 2 * TILE_B + off) =
                *(const uint4*)(Bh + (size_t)(n0 + row) * K + c16 * 8);
            if (PROD >= 2)
                *(uint4*)(st + 3 * TILE_B + off) =
                    *(const uint4*)(Bl + (size_t)(n0 + row) * K + c16 * 8);
        }
    }
    __syncthreads();

    for (int c = 0; c < NCHUNK; c++) {
        const int buf = c & 1;
        const uint32_t sAh = sb + buf * STAGE_B;
        const uint32_t sAl = sAh + TILE_B;
        const uint32_t sBh = sAh + 2 * TILE_B;
        const uint32_t sBl = sAh + 3 * TILE_B;

        float4 ra[8];
        uint4  rbh[4], rbl[4];
        if (c + 1 < NCHUNK) {
            const float* Ap = A + (size_t)m0 * K + (c + 1) * 64;
#pragma unroll
            for (int it = 0; it < 8; it++) {
                int f = tid + (it << 8);
                int row = f >> 4;
                int cg  = (f & 15) << 2;
                ra[it] = *(const float4*)(Ap + (size_t)row * K + cg);
            }
            const __half* Bhp = Bh + (size_t)n0 * K + (c + 1) * 64;
            const __half* Blp = Bl + (size_t)n0 * K + (c + 1) * 64;
#pragma unroll
            for (int i = 0; i < 4; i++) {
                int idx = tid * 4 + i;
                int row = idx >> 3;
                int c16 = idx & 7;
                rbh[i] = *(const uint4*)(Bhp + (size_t)row * K + c16 * 8);
                if (PROD >= 2)
                    rbl[i] = *(const uint4*)(Blp + (size_t)row * K + c16 * 8);
            }
        }

#pragma unroll
        for (int ks = 0; ks < 4; ks++) {
            uint32_t ah[4][4], al[4][4], bh[4][2], bl[4][2];
#pragma unroll
            for (int mt = 0; mt < 4; mt++) {
                uint32_t off = (uint32_t)((aRow + mt * 16) * 128) +
                               (((uint32_t)(ks * 32 + aKb)) ^ aXor);
                ldmx4(ah[mt], sAh + off);
                if (PROD == 3) ldmx4(al[mt], sAl + off);
            }
#pragma unroll
            for (int np = 0; np < 2; np++) {
                uint32_t off = (uint32_t)((bRow + np * 16) * 128) +
                               (((uint32_t)(ks * 32 + bKb)) ^ bXor);
                uint32_t r[4];
                ldmx4(r, sBh + off);
                bh[2*np][0] = r[0]; bh[2*np][1] = r[1];
                bh[2*np+1][0] = r[2]; bh[2*np+1][1] = r[3];
                if (PROD >= 2) {
                    ldmx4(r, sBl + off);
                    bl[2*np][0] = r[0]; bl[2*np][1] = r[1];
                    bl[2*np+1][0] = r[2]; bl[2*np+1][1] = r[3];
                }
            }
#pragma unroll
            for (int mt = 0; mt < 4; mt++)
#pragma unroll
                for (int nt = 0; nt < 4; nt++) {
                    mma_f16(acc[mt][nt], ah[mt], bh[nt]);
                    if (PROD >= 2) mma_f16(acc[mt][nt], ah[mt], bl[nt]);
                    if (PROD == 3) mma_f16(acc[mt][nt], al[mt], bh[nt]);
                }
        }

        if (c + 1 < NCHUNK) {
            char* st = smem + (buf ^ 1) * STAGE_B;
#pragma unroll
            for (int it = 0; it < 8; it++) {
                int f = tid + (it << 8);
                int row = f >> 4;
                int cg  = (f & 15) << 2;
                uint32_t off = SMEM_SWIZZLE_128B((uint32_t)(row * 128 + cg * 2));
                uint2 h, l;
                if (PROD == 3) { split4h(ra[it], h, l); *(uint2*)(st + TILE_B + off) = l; }
                else           { cvt4h(ra[it], h); }
                *(uint2*)(st + off) = h;
            }
#pragma unroll
            for (int i = 0; i < 4; i++) {
                int idx = tid * 4 + i;
                int row = idx >> 3;
                int c16 = idx & 7;
                uint32_t off = SMEM_SWIZZLE_128B((uint32_t)(row * 128 + c16 * 16));
                *(uint4*)(st + 2 * TILE_B + off) = rbh[i];
                if (PROD >= 2) *(uint4*)(st + 3 * TILE_B + off) = rbl[i];
            }
        }
        __syncthreads();
    }

#pragma unroll
    for (int mt = 0; mt < 4; mt++) {
        int r0 = m0 + wm * 64 + mt * 16 + (lane >> 2);
#pragma unroll
        for (int nt = 0; nt < 4; nt++) {
            int c0 = n0 + wn * 32 + nt * 8 + (lane & 3) * 2;
            *(float2*)(C + (size_t)r0 * DIM + c0) =
                make_float2(acc[mt][nt][0], acc[mt][nt][1]);
            *(float2*)(C + (size_t)(r0 + 8) * DIM + c0) =
                make_float2(acc[mt][nt][2], acc[mt][nt][3]);
        }
    }
}

// ===========================================================================
// fused rope + fp16 convert: Q,K roped -> fp16 rn; V -> fp16 hi/lo split.
// one thread per pair p (512 per row).
// ===========================================================================
__global__ __launch_bounds__(256) void rope_split()
{
    int idx = blockIdx.x * blockDim.x + threadIdx.x;
    if (idx >= S_LEN * (DIM / 2)) return;
    int s = idx >> 9;
    int p = idx & 511;
    int i = p & 31;

    float e   = (float)(-(double)(2 * i) * 13.287712379549449 / 64.0);
    float inv = exp2f(e);
    float ang = (float)s * inv;
    float sn, cs;
    sincosf(ang, &sn, &cs);

    size_t off = (size_t)s * DIM + 2 * p;
    size_t w   = off >> 1;

    float2 q = *(const float2*)(g_Q + off);
    ((uint32_t*)g_Q16)[w] = pack2h(q.x * cs - q.y * sn, q.x * sn + q.y * cs);

    float2 k = *(const float2*)(g_K + off);
    ((uint32_t*)g_K16)[w] = pack2h(k.x * cs - k.y * sn, k.x * sn + k.y * cs);

    float2 v = *(const float2*)(g_V + off);
    uint32_t hi, lo;
    pack_split2h(v.x, v.y, hi, lo);
    ((uint32_t*)g_Vh16)[w] = hi;
    ((uint32_t*)g_Vl16)[w] = lo;
}

// ===========================================================================
// Sliding-window attention (lean, R12): QK 1-product fp16, PV 3-product.
// Interior k-tiles skip mask compare/select (mask provably all-true there).
// CTA = (128 q, 1 head), 8 warps. smem: Q 16K | K 8K | Vh 8K | Vl 8K = 40KB.
// ===========================================================================
#define ASMEM_TOTAL 40960
#define OFF_Q  0
#define OFF_K  16384
#define OFF_VH 24576
#define OFF_VL 32768

__global__ __launch_bounds__(256) void swa_mma()
{
    extern __shared__ __align__(1024) char smem[];
    const uint32_t sb = smem_to_u32(smem);
    const int h   = blockIdx.y;
    const int q0  = blockIdx.x * 128;
    const int tid = threadIdx.x;
    const int w   = tid >> 5;
    const int lane = tid & 31;

    // ---- stage Q tile (raw fp16 copy) ----
#pragma unroll
    for (int i = 0; i < 4; i++) {
        int idx = tid * 4 + i;
        int row = idx >> 3;
        int c16 = idx & 7;
        uint32_t off = SMEM_SWIZZLE_128B((uint32_t)(row * 128 + c16 * 16));
        *(uint4*)(smem + OFF_Q + off) =
            *(const uint4*)(g_Q16 + (size_t)(q0 + row) * DIM + h * HD + c16 * 8);
    }
    __syncthreads();

    // ---- preload Q fragments ----
    uint32_t qh[4][4];
    {
        const int aRow = w * 16 + (lane & 15);
        const uint32_t aSw = (uint32_t)((aRow & 7) << 4);
#pragma unroll
        for (int ks = 0; ks < 4; ks++) {
            uint32_t off = (uint32_t)(aRow * 128) +
                           (((uint32_t)(ks * 32 + ((lane >> 4) & 1) * 16)) ^ aSw);
            ldmx4(qh[ks], sb + OFF_Q + off);
        }
    }

    const int bRow = (lane & 7) + ((lane >> 4) & 1) * 8;
    const int bKb  = ((lane >> 3) & 1) * 16;
    const uint32_t bSw = (uint32_t)((bRow & 7) << 4);
    const int vRow = (lane & 7) + ((lane >> 3) & 1) * 8;
    const int vCb  = ((lane >> 4) & 1) * 16;
    const uint32_t vSw = (uint32_t)((vRow & 7) << 4);

    float m0 = -1e30f, m1 = -1e30f, l0 = 0.f, l1 = 0.f;
    float oacc[8][4];
#pragma unroll
    for (int j = 0; j < 8; j++)
#pragma unroll
        for (int q = 0; q < 4; q++) oacc[j][q] = 0.f;

    const int kt_begin = (q0 >= WIN) ? ((q0 - WIN + 1) >> 6) : 0;
    const int kt_end   = (q0 + 127) >> 6;
    const int kt_diag  = q0 >> 6;              // first tile with causal masking
    const float sc = 0.125f * 1.4426950408889634f;

    // ---- stage first K/V tile (raw fp16 copies) ----
    {
        const int k0 = kt_begin << 6;
#pragma unroll
        for (int i = 0; i < 2; i++) {
            int idx = tid * 2 + i;
            int row = idx >> 3;
            int c16 = idx & 7;
            uint32_t off = SMEM_SWIZZLE_128B((uint32_t)(row * 128 + c16 * 16));
            size_t g = (size_t)(k0 + row) * DIM + h * HD + c16 * 8;
            *(uint4*)(smem + OFF_K  + off) = *(const uint4*)(g_K16  + g);
            *(uint4*)(smem + OFF_VH + off) = *(const uint4*)(g_Vh16 + g);
            *(uint4*)(smem + OFF_VL + off) = *(const uint4*)(g_Vl16 + g);
        }
    }
    __syncthreads();

    const int qg0 = q0 + w * 16 + (lane >> 2);
    const int qg1 = qg0 + 8;

    for (int kt = kt_begin; kt <= kt_end; kt++) {
        const int k0 = kt << 6;
        // mask needed only near window left edge or causal diagonal
        const bool need_mask = (kt <= kt_begin + 1) || (kt >= kt_diag);

        // prefetch next tile into registers
        uint4 rk[2], rvh[2], rvl[2];
        if (kt < kt_end) {
            const int kn = (kt + 1) << 6;
#pragma unroll
            for (int i = 0; i < 2; i++) {
                int idx = tid * 2 + i;
                int row = idx >> 3;
                int c16 = idx & 7;
                size_t g = (size_t)(kn + row) * DIM + h * HD + c16 * 8;
                rk[i]  = *(const uint4*)(g_K16  + g);
                rvh[i] = *(const uint4*)(g_Vh16 + g);
                rvl[i] = *(const uint4*)(g_Vl16 + g);
            }
        }

        // ---- scores: 1-product fp16 QK ----
        float sacc[8][4];
#pragma unroll
        for (int j = 0; j < 8; j++)
#pragma unroll
            for (int q = 0; q < 4; q++) sacc[j][q] = 0.f;

#pragma unroll
        for (int ks = 0; ks < 4; ks++) {
#pragma unroll
            for (int np = 0; np < 4; np++) {
                uint32_t off = (uint32_t)((np * 16 + bRow) * 128) +
                               (((uint32_t)(ks * 32 + bKb)) ^ bSw);
                uint32_t kh4[4];
                ldmx4(kh4, sb + OFF_K + off);
                mma_f16(sacc[2*np],   qh[ks], kh4);
                mma_f16(sacc[2*np+1], qh[ks], kh4 + 2);
            }
        }

        // ---- mask + scale ----
        if (need_mask) {
#pragma unroll
            for (int j = 0; j < 8; j++) {
                int kg = k0 + 8 * j + ((lane & 3) << 1);
                sacc[j][0] = (kg   <= qg0 && kg   + WIN > qg0) ? sacc[j][0] * sc : -1e30f;
                sacc[j][1] = (kg+1 <= qg0 && kg+1 + WIN > qg0) ? sacc[j][1] * sc : -1e30f;
                sacc[j][2] = (kg   <= qg1 && kg   + WIN > qg1) ? sacc[j][2] * sc : -1e30f;
                sacc[j][3] = (kg+1 <= qg1 && kg+1 + WIN > qg1) ? sacc[j][3] * sc : -1e30f;
            }
        } else {
#pragma unroll
            for (int j = 0; j < 8; j++) {
                sacc[j][0] *= sc; sacc[j][1] *= sc;
                sacc[j][2] *= sc; sacc[j][3] *= sc;
            }
        }

        // ---- online softmax ----
        float t0 = -1e30f, t1 = -1e30f;
#pragma unroll
        for (int j = 0; j < 8; j++) {
            t0 = fmaxf(t0, fmaxf(sacc[j][0], sacc[j][1]));
            t1 = fmaxf(t1, fmaxf(sacc[j][2], sacc[j][3]));
        }
        t0 = fmaxf(t0, __shfl_xor_sync(0xffffffffu, t0, 1));
        t0 = fmaxf(t0, __shfl_xor_sync(0xffffffffu, t0, 2));
        t1 = fmaxf(t1, __shfl_xor_sync(0xffffffffu, t1, 1));
        t1 = fmaxf(t1, __shfl_xor_sync(0xffffffffu, t1, 2));
        float mn0 = fmaxf(m0, t0), mn1 = fmaxf(m1, t1);
        float c0 = exp2f_fast(m0 - mn0), c1 = exp2f_fast(m1 - mn1);
        m0 = mn0; m1 = mn1;

        float s0 = 0.f, s1 = 0.f;
#pragma unroll
        for (int j = 0; j < 8; j++) {
            float p0 = exp2f_fast(sacc[j][0] - m0);
            float p1 = exp2f_fast(sacc[j][1] - m0);
            float p2 = exp2f_fast(sacc[j][2] - m1);
            float p3 = exp2f_fast(sacc[j][3] - m1);
            sacc[j][0] = p0; sacc[j][1] = p1; sacc[j][2] = p2; sacc[j][3] = p3;
            s0 += p0 + p1; s1 += p2 + p3;
        }
        s0 += __shfl_xor_sync(0xffffffffu, s0, 1);
        s0 += __shfl_xor_sync(0xffffffffu, s0, 2);
        s1 += __shfl_xor_sync(0xffffffffu, s1, 1);
        s1 += __shfl_xor_sync(0xffffffffu, s1, 2);
        l0 = l0 * c0 + s0;
        l1 = l1 * c1 + s1;
#pragma unroll
        for (int j = 0; j < 8; j++) {
            oacc[j][0] *= c0; oacc[j][1] *= c0;
            oacc[j][2] *= c1; oacc[j][3] *= c1;
        }

        // ---- pack P (fp16 hi/lo) ----
        uint32_t aPh[4][4], aPl[4][4];
#pragma unroll
        for (int t = 0; t < 4; t++) {
            pack_split2h(sacc[2*t][0],   sacc[2*t][1],   aPh[t][0], aPl[t][0]);
            pack_split2h(sacc[2*t][2],   sacc[2*t][3],   aPh[t][1], aPl[t][1]);
            pack_split2h(sacc[2*t+1][0], sacc[2*t+1][1], aPh[t][2], aPl[t][2]);
            pack_split2h(sacc[2*t+1][2], sacc[2*t+1][3], aPh[t][3], aPl[t][3]);
        }

        // ---- O += P V (3-product fp16) ----
#pragma unroll
        for (int t = 0; t < 4; t++) {
#pragma unroll
            for (int j2 = 0; j2 < 4; j2++) {
                uint32_t off = (uint32_t)((t * 16 + vRow) * 128) +
                               (((uint32_t)(j2 * 32 + vCb)) ^ vSw);
                uint32_t vh4[4], vl4[4];
                ldmx4t(vh4, sb + OFF_VH + off);
                ldmx4t(vl4, sb + OFF_VL + off);
                mma_f16(oacc[2*j2],   aPh[t], vh4);
                mma_f16(oacc[2*j2],   aPh[t], vl4);
                mma_f16(oacc[2*j2],   aPl[t], vh4);
                mma_f16(oacc[2*j2+1], aPh[t], vh4 + 2);
                mma_f16(oacc[2*j2+1], aPh[t], vl4 + 2);
                mma_f16(oacc[2*j2+1], aPl[t], vh4 + 2);
            }
        }

        __syncthreads();
        if (kt < kt_end) {
#pragma unroll
            for (int i = 0; i < 2; i++) {
                int idx = tid * 2 + i;
                int row = idx >> 3;
                int c16 = idx & 7;
                uint32_t off = SMEM_SWIZZLE_128B((uint32_t)(row * 128 + c16 * 16));
                *(uint4*)(smem + OFF_K  + off) = rk[i];
                *(uint4*)(smem + OFF_VH + off) = rvh[i];
                *(uint4*)(smem + OFF_VL + off) = rvl[i];
            }
            __syncthreads();
        }
    }

    // ---- epilogue: O /= l ----
    float inv0 = 1.f / l0, inv1 = 1.f / l1;
    const int r0g = q0 + w * 16 + (lane >> 2);
#pragma unroll
    for (int j = 0; j < 8; j++) {
        int c0 = h * HD + 8 * j + ((lane & 3) << 1);
        *(float2*)(g_O + (size_t)r0g * DIM + c0) =
            make_float2(oacc[j][0] * inv0, oacc[j][1] * inv0);
        *(float2*)(g_O + (size_t)(r0g + 8) * DIM + c0) =
            make_float2(oacc[j][2] * inv1, oacc[j][3] * inv1);
    }
}

// ---------------------------------------------------------------------------
extern "C" void kernel_launch(void* const* d_in, const int* in_sizes, int n_in,
                              void* d_out, int out_size)
{
    const float* x  = (const float*)d_in[0];
    const float* Wq = (const float*)d_in[1];
    const float* Wk = (const float*)d_in[2];
    const float* Wv = (const float*)d_in[3];
    const float* Wo = (const float*)d_in[4];
    float* out = (float*)d_out;
    (void)in_sizes; (void)n_in; (void)out_size;

    static float *pQ = nullptr, *pK = nullptr, *pV = nullptr, *pO = nullptr;
    static __half *pWh, *pWl;
    if (!pQ) {
        cudaGetSymbolAddress((void**)&pQ,  g_Q);
        cudaGetSymbolAddress((void**)&pK,  g_K);
        cudaGetSymbolAddress((void**)&pV,  g_V);
        cudaGetSymbolAddress((void**)&pO,  g_O);
        cudaGetSymbolAddress((void**)&pWh, g_Wh);
        cudaGetSymbolAddress((void**)&pWl, g_Wl);
        cudaFuncSetAttribute(gemm_f16<1>, cudaFuncAttributeMaxDynamicSharedMemorySize,
                             GSMEM_TOTAL);
        cudaFuncSetAttribute(gemm_f16<2>, cudaFuncAttributeMaxDynamicSharedMemorySize,
                             GSMEM_TOTAL);
        cudaFuncSetAttribute(gemm_f16<3>, cudaFuncAttributeMaxDynamicSharedMemorySize,
                             GSMEM_TOTAL);
        cudaFuncSetAttribute(swa_mma, cudaFuncAttributeMaxDynamicSharedMemorySize,
                             ASMEM_TOTAL);
    }

    split_all<<<(4 * NW / 2) / 256, 256>>>(Wq, Wk, Wv, Wo);

    dim3 gg(DIM / 128, S_LEN / 128);   // (8, 64)
    gemm_f16<1><<<gg, 256, GSMEM_TOTAL>>>(x, pWh + 0 * NW, pWl + 0 * NW, pQ);
    gemm_f16<1><<<gg, 256, GSMEM_TOTAL>>>(x, pWh + 1 * NW, pWl + 1 * NW, pK);
    gemm_f16<2><<<gg, 256, GSMEM_TOTAL>>>(x, pWh + 2 * NW, pWl + 2 * NW, pV);

    rope_split<<<(S_LEN * (DIM / 2)) / 256, 256>>>();

    swa_mma<<<dim3(S_LEN / 128, NH), 256, ASMEM_TOTAL>>>();

    gemm_f16<3><<<gg, 256, GSMEM_TOTAL>>>(pO, pWh + 3 * NW, pWl + 3 * NW, out);
}

// round 14
// speedup vs baseline: 1.0603x; 1.0016x over previous
#include <cuda_runtime.h>
#include <cuda_fp16.h>
#include <cstdint>

#define S_LEN 8192
#define DIM   1024
#define NH    16
#define HD    64
#define WIN   512

// Scratch (device globals: allocation-guard safe).
__device__ float  g_Q[S_LEN * DIM];
__device__ float  g_K[S_LEN * DIM];
__device__ float  g_V[S_LEN * DIM];
__device__ float  g_O[S_LEN * DIM];
__device__ __half g_Q16[S_LEN * DIM];
__device__ __half g_K16[S_LEN * DIM];
__device__ __half g_Vh16[S_LEN * DIM];
__device__ __half g_Vl16[S_LEN * DIM];
__device__ __half g_Wh[4 * DIM * DIM];
__device__ __half g_Wl[4 * DIM * DIM];

// ===========================================================================
// helpers (legacy mma.sync path: tcgen05 gated off at PTX target sm_100)
// ===========================================================================
__device__ __forceinline__ uint32_t smem_to_u32(const void* p) {
    uint32_t a;
    asm("{ .reg .u64 t; cvta.to.shared.u64 t, %1; cvt.u32.u64 %0, t; }"
        : "=r"(a) : "l"(p));
    return a;
}
__device__ __forceinline__ void ldmx4(uint32_t* r, uint32_t addr) {
    asm volatile("ldmatrix.sync.aligned.m8n8.x4.shared.b16 {%0,%1,%2,%3}, [%4];"
        : "=r"(r[0]), "=r"(r[1]), "=r"(r[2]), "=r"(r[3]) : "r"(addr));
}
__device__ __forceinline__ void ldmx4t(uint32_t* r, uint32_t addr) {
    asm volatile("ldmatrix.sync.aligned.m8n8.x4.trans.shared.b16 {%0,%1,%2,%3}, [%4];"
        : "=r"(r[0]), "=r"(r[1]), "=r"(r[2]), "=r"(r[3]) : "r"(addr));
}
__device__ __forceinline__ void mma_f16(float* d, const uint32_t* a, const uint32_t* b) {
    asm volatile(
        "mma.sync.aligned.m16n8k16.row.col.f32.f16.f16.f32 "
        "{%0,%1,%2,%3}, {%4,%5,%6,%7}, {%8,%9}, {%0,%1,%2,%3};"
        : "+f"(d[0]), "+f"(d[1]), "+f"(d[2]), "+f"(d[3])
        : "r"(a[0]), "r"(a[1]), "r"(a[2]), "r"(a[3]), "r"(b[0]), "r"(b[1]));
}
#define SMEM_SWIZZLE_128B(byte_offset) \
    ((byte_offset) ^ (((byte_offset) >> 3) & 0x70))

__device__ __forceinline__ uint32_t pack2h(float a, float b) {
    __half2 h = __floats2half2_rn(a, b);
    return *reinterpret_cast<uint32_t*>(&h);
}
__device__ __forceinline__ void pack_split2h(float e0, float e1,
                                             uint32_t& hi, uint32_t& lo) {
    __half2 h = __floats2half2_rn(e0, e1);
    float r0 = e0 - __low2float(h);
    float r1 = e1 - __high2float(h);
    __half2 l = __floats2half2_rn(r0, r1);
    hi = *reinterpret_cast<uint32_t*>(&h);
    lo = *reinterpret_cast<uint32_t*>(&l);
}
__device__ __forceinline__ void cvt4h(float4 v, uint2& hi) {
    hi.x = pack2h(v.x, v.y);
    hi.y = pack2h(v.z, v.w);
}
__device__ __forceinline__ void split4h(float4 v, uint2& hi, uint2& lo) {
    __half2 a = __floats2half2_rn(v.x, v.y);
    __half2 b = __floats2half2_rn(v.z, v.w);
    hi.x = *reinterpret_cast<uint32_t*>(&a);
    hi.y = *reinterpret_cast<uint32_t*>(&b);
    lo.x = pack2h(v.x - __low2float(a), v.y - __high2float(a));
    lo.y = pack2h(v.z - __low2float(b), v.w - __high2float(b));
}
// fast exp2 on the FMA pipe (no MUFU)
__device__ __forceinline__ float exp2f_fast(float x) {
    x = fmaxf(x, -126.0f);
    float n = rintf(x);
    float f = x - n;
    float p = 0.00133335581f;
    p = fmaf(p, f, 0.00961812911f);
    p = fmaf(p, f, 0.05550410866f);
    p = fmaf(p, f, 0.24022650700f);
    p = fmaf(p, f, 0.69314718056f);
    p = fmaf(p, f, 1.0f);
    return p * __int_as_float(((int)n + 127) << 23);
}

// ===========================================================================
// weight split: all four fp32 weights -> contiguous (hi, lo) fp16 arrays
// ===========================================================================
#define NW (DIM * DIM)
__global__ __launch_bounds__(256) void split_all(const float* __restrict__ Wq,
                                                 const float* __restrict__ Wk,
                                                 const float* __restrict__ Wv,
                                                 const float* __restrict__ Wo)
{
    int i = blockIdx.x * blockDim.x + threadIdx.x;
    int sel = i / (NW / 2);
    int off = i - sel * (NW / 2);
    const float* src = (sel == 0) ? Wq : (sel == 1) ? Wk : (sel == 2) ? Wv : Wo;
    float2 v = *(const float2*)(src + 2 * (size_t)off);
    uint32_t hi, lo;
    pack_split2h(v.x, v.y, hi, lo);
    ((uint32_t*)g_Wh)[i] = hi;
    ((uint32_t*)g_Wl)[i] = lo;
}

// ===========================================================================
// GEMM NT, PROD products (R11 verbatim): C = A * B^T.
//  PROD=1: Ah*Bh ; PROD=2: Ah*(Bh+Bl) ; PROD=3: (Ah+Al)*Bh + Ah*Bl
// ===========================================================================
#define TILE_B 16384
#define STAGE_B (4 * TILE_B)
#define GSMEM_TOTAL (2 * STAGE_B)
#define NCHUNK 16

template<int PROD>
__global__ __launch_bounds__(256) void gemm_f16(const float* __restrict__ A,
                                                const __half* __restrict__ Bh,
                                                const __half* __restrict__ Bl,
                                                float* __restrict__ C)
{
    extern __shared__ __align__(1024) char smem[];
    const uint32_t sb = smem_to_u32(smem);
    const int tid  = threadIdx.x;
    const int wid  = tid >> 5;
    const int lane = tid & 31;
    const int m0   = blockIdx.y * 128;
    const int n0   = blockIdx.x * 128;
    const int wm   = wid & 1;
    const int wn   = wid >> 1;
    const int K    = DIM;

    const int aRow = wm * 64 + (lane & 15);
    const int aKb  = ((lane >> 4) & 1) * 16;
    const uint32_t aXor = (uint32_t)((aRow & 7) << 4);
    const int bRow = wn * 32 + (lane & 7) + ((lane >> 4) & 1) * 8;
    const int bKb  = ((lane >> 3) & 1) * 16;
    const uint32_t bXor = (uint32_t)((bRow & 7) << 4);

    float acc[4][4][4];
#pragma unroll
    for (int mt = 0; mt < 4; mt++)
#pragma unroll
        for (int nt = 0; nt < 4; nt++)
#pragma unroll
            for (int q = 0; q < 4; q++) acc[mt][nt][q] = 0.f;

    {
        char* st = smem;
#pragma unroll
        for (int it = 0; it < 8; it++) {
            int f = tid + (it << 8);
            int row = f >> 4;
            int cg  = (f & 15) << 2;
            uint32_t off = SMEM_SWIZZLE_128B((uint32_t)(row * 128 + cg * 2));
            float4 va = *(const float4*)(A + (size_t)(m0 + row) * K + cg);
            uint2 h, l;
            if (PROD == 3) { split4h(va, h, l); *(uint2*)(st + TILE_B + off) = l; }
            else           { cvt4h(va, h); }
            *(uint2*)(st + off) = h;
        }
#pragma unroll
        for (int i = 0; i < 4; i++) {
            int idx = tid * 4 + i;
            int row = idx >> 3;
            int c16 = idx & 7;
            uint32_t off = SMEM_SWIZZLE_128B((uint32_t)(row * 128 + c16 * 16));
            *(uint4*)(st + 2 * TILE_B + off) =
                *(const uint4*)(Bh + (size_t)(n0 + row) * K + c16 * 8);
            if (PROD >= 2)
                *(uint4*)(st + 3 * TILE_B + off) =
                    *(const uint4*)(Bl + (size_t)(n0 + row) * K + c16 * 8);
        }
    }
    __syncthreads();

    for (int c = 0; c < NCHUNK; c++) {
        const int buf = c & 1;
        const uint32_t sAh = sb + buf * STAGE_B;
        const uint32_t sAl = sAh + TILE_B;
        const uint32_t sBh = sAh + 2 * TILE_B;
        const uint32_t sBl = sAh + 3 * TILE_B;

        float4 ra[8];
        uint4  rbh[4], rbl[4];
        if (c + 1 < NCHUNK) {
            const float* Ap = A + (size_t)m0 * K + (c + 1) * 64;
#pragma unroll
            for (int it = 0; it < 8; it++) {
                int f = tid + (it << 8);
                int row = f >> 4;
                int cg  = (f & 15) << 2;
                ra[it] = *(const float4*)(Ap + (size_t)row * K + cg);
            }
            const __half* Bhp = Bh + (size_t)n0 * K + (c + 1) * 64;
            const __half* Blp = Bl + (size_t)n0 * K + (c + 1) * 64;
#pragma unroll
            for (int i = 0; i < 4; i++) {
                int idx = tid * 4 + i;
                int row = idx >> 3;
                int c16 = idx & 7;
                rbh[i] = *(const uint4*)(Bhp + (size_t)row * K + c16 * 8);
                if (PROD >= 2)
                    rbl[i] = *(const uint4*)(Blp + (size_t)row * K + c16 * 8);
            }
        }

#pragma unroll
        for (int ks = 0; ks < 4; ks++) {
            uint32_t ah[4][4], al[4][4], bh[4][2], bl[4][2];
#pragma unroll
            for (int mt = 0; mt < 4; mt++) {
                uint32_t off = (uint32_t)((aRow + mt * 16) * 128) +
                               (((uint32_t)(ks * 32 + aKb)) ^ aXor);
                ldmx4(ah[mt], sAh + off);
                if (PROD == 3) ldmx4(al[mt], sAl + off);
            }
#pragma unroll
            for (int np = 0; np < 2; np++) {
                uint32_t off = (uint32_t)((bRow + np * 16) * 128) +
                               (((uint32_t)(ks * 32 + bKb)) ^ bXor);
                uint32_t r[4];
                ldmx4(r, sBh + off);
                bh[2*np][0] = r[0]; bh[2*np][1] = r[1];
                bh[2*np+1][0] = r[2]; bh[2*np+1][1] = r[3];
                if (PROD >= 2) {
                    ldmx4(r, sBl + off);
                    bl[2*np][0] = r[0]; bl[2*np][1] = r[1];
                    bl[2*np+1][0] = r[2]; bl[2*np+1][1] = r[3];
                }
            }
#pragma unroll
            for (int mt = 0; mt < 4; mt++)
#pragma unroll
                for (int nt = 0; nt < 4; nt++) {
                    mma_f16(acc[mt][nt], ah[mt], bh[nt]);
                    if (PROD >= 2) mma_f16(acc[mt][nt], ah[mt], bl[nt]);
                    if (PROD == 3) mma_f16(acc[mt][nt], al[mt], bh[nt]);
                }
        }

        if (c + 1 < NCHUNK) {
            char* st = smem + (buf ^ 1) * STAGE_B;
#pragma unroll
            for (int it = 0; it < 8; it++) {
                int f = tid + (it << 8);
                int row = f >> 4;
                int cg  = (f & 15) << 2;
                uint32_t off = SMEM_SWIZZLE_128B((uint32_t)(row * 128 + cg * 2));
                uint2 h, l;
                if (PROD == 3) { split4h(ra[it], h, l); *(uint2*)(st + TILE_B + off) = l; }
                else           { cvt4h(ra[it], h); }
                *(uint2*)(st + off) = h;
            }
#pragma unroll
            for (int i = 0; i < 4; i++) {
                int idx = tid * 4 + i;
                int row = idx >> 3;
                int c16 = idx & 7;
                uint32_t off = SMEM_SWIZZLE_128B((uint32_t)(row * 128 + c16 * 16));
                *(uint4*)(st + 2 * TILE_B + off) = rbh[i];
                if (PROD >= 2) *(uint4*)(st + 3 * TILE_B + off) = rbl[i];
            }
        }
        __syncthreads();
    }

#pragma unroll
    for (int mt = 0; mt < 4; mt++) {
        int r0 = m0 + wm * 64 + mt * 16 + (lane >> 2);
#pragma unroll
        for (int nt = 0; nt < 4; nt++) {
            int c0 = n0 + wn * 32 + nt * 8 + (lane & 3) * 2;
            *(float2*)(C + (size_t)r0 * DIM + c0) =
                make_float2(acc[mt][nt][0], acc[mt][nt][1]);
            *(float2*)(C + (size_t)(r0 + 8) * DIM + c0) =
                make_float2(acc[mt][nt][2], acc[mt][nt][3]);
        }
    }
}

// ===========================================================================
// fused rope + fp16 convert: Q,K roped -> fp16 rn; V -> fp16 hi/lo split.
// one thread per pair p (512 per row).
// ===========================================================================
__global__ __launch_bounds__(256) void rope_split()
{
    int idx = blockIdx.x * blockDim.x + threadIdx.x;
    if (idx >= S_LEN * (DIM / 2)) return;
    int s = idx >> 9;
    int p = idx & 511;
    int i = p & 31;

    float e   = (float)(-(double)(2 * i) * 13.287712379549449 / 64.0);
    float inv = exp2f(e);
    float ang = (float)s * inv;
    float sn, cs;
    sincosf(ang, &sn, &cs);

    size_t off = (size_t)s * DIM + 2 * p;
    size_t w   = off >> 1;

    float2 q = *(const float2*)(g_Q + off);
    ((uint32_t*)g_Q16)[w] = pack2h(q.x * cs - q.y * sn, q.x * sn + q.y * cs);

    float2 k = *(const float2*)(g_K + off);
    ((uint32_t*)g_K16)[w] = pack2h(k.x * cs - k.y * sn, k.x * sn + k.y * cs);

    float2 v = *(const float2*)(g_V + off);
    uint32_t hi, lo;
    pack_split2h(v.x, v.y, hi, lo);
    ((uint32_t*)g_Vh16)[w] = hi;
    ((uint32_t*)g_Vl16)[w] = lo;
}

// ===========================================================================
// Sliding-window attention (lean, R12): QK 1-product fp16, PV 3-product.
// Interior k-tiles skip mask compare/select (mask provably all-true there).
// CTA = (128 q, 1 head), 8 warps. smem: Q 16K | K 8K | Vh 8K | Vl 8K = 40KB.
// ===========================================================================
#define ASMEM_TOTAL 40960
#define OFF_Q  0
#define OFF_K  16384
#define OFF_VH 24576
#define OFF_VL 32768

__global__ __launch_bounds__(256) void swa_mma()
{
    extern __shared__ __align__(1024) char smem[];
    const uint32_t sb = smem_to_u32(smem);
    const int h   = blockIdx.y;
    const int q0  = blockIdx.x * 128;
    const int tid = threadIdx.x;
    const int w   = tid >> 5;
    const int lane = tid & 31;

    // ---- stage Q tile (raw fp16 copy) ----
#pragma unroll
    for (int i = 0; i < 4; i++) {
        int idx = tid * 4 + i;
        int row = idx >> 3;
        int c16 = idx & 7;
        uint32_t off = SMEM_SWIZZLE_128B((uint32_t)(row * 128 + c16 * 16));
        *(uint4*)(smem + OFF_Q + off) =
            *(const uint4*)(g_Q16 + (size_t)(q0 + row) * DIM + h * HD + c16 * 8);
    }
    __syncthreads();

    // ---- preload Q fragments ----
    uint32_t qh[4][4];
    {
        const int aRow = w * 16 + (lane & 15);
        const uint32_t aSw = (uint32_t)((aRow & 7) << 4);
#pragma unroll
        for (int ks = 0; ks < 4; ks++) {
            uint32_t off = (uint32_t)(aRow * 128) +
                           (((uint32_t)(ks * 32 + ((lane >> 4) & 1) * 16)) ^ aSw);
            ldmx4(qh[ks], sb + OFF_Q + off);
        }
    }

    const int bRow = (lane & 7) + ((lane >> 4) & 1) * 8;
    const int bKb  = ((lane >> 3) & 1) * 16;
    const uint32_t bSw = (uint32_t)((bRow & 7) << 4);
    const int vRow = (lane & 7) + ((lane >> 3) & 1) * 8;
    const int vCb  = ((lane >> 4) & 1) * 16;
    const uint32_t vSw = (uint32_t)((vRow & 7) << 4);

    float m0 = -1e30f, m1 = -1e30f, l0 = 0.f, l1 = 0.f;
    float oacc[8][4];
#pragma unroll
    for (int j = 0; j < 8; j++)
#pragma unroll
        for (int q = 0; q < 4; q++) oacc[j][q] = 0.f;

    const int kt_begin = (q0 >= WIN) ? ((q0 - WIN + 1) >> 6) : 0;
    const int kt_end   = (q0 + 127) >> 6;
    const int kt_diag  = q0 >> 6;              // first tile with causal masking
    const float sc = 0.125f * 1.4426950408889634f;

    // ---- stage first K/V tile (raw fp16 copies) ----
    {
        const int k0 = kt_begin << 6;
#pragma unroll
        for (int i = 0; i < 2; i++) {
            int idx = tid * 2 + i;
            int row = idx >> 3;
            int c16 = idx & 7;
            uint32_t off = SMEM_SWIZZLE_128B((uint32_t)(row * 128 + c16 * 16));
            size_t g = (size_t)(k0 + row) * DIM + h * HD + c16 * 8;
            *(uint4*)(smem + OFF_K  + off) = *(const uint4*)(g_K16  + g);
            *(uint4*)(smem + OFF_VH + off) = *(const uint4*)(g_Vh16 + g);
            *(uint4*)(smem + OFF_VL + off) = *(const uint4*)(g_Vl16 + g);
        }
    }
    __syncthreads();

    const int qg0 = q0 + w * 16 + (lane >> 2);
    const int qg1 = qg0 + 8;

    for (int kt = kt_begin; kt <= kt_end; kt++) {
        const int k0 = kt << 6;
        // mask needed only near window left edge or causal diagonal
        const bool need_mask = (kt <= kt_begin + 1) || (kt >= kt_diag);

        // prefetch next tile into registers
        uint4 rk[2], rvh[2], rvl[2];
        if (kt < kt_end) {
            const int kn = (kt + 1) << 6;
#pragma unroll
            for (int i = 0; i < 2; i++) {
                int idx = tid * 2 + i;
                int row = idx >> 3;
                int c16 = idx & 7;
                size_t g = (size_t)(kn + row) * DIM + h * HD + c16 * 8;
                rk[i]  = *(const uint4*)(g_K16  + g);
                rvh[i] = *(const uint4*)(g_Vh16 + g);
                rvl[i] = *(const uint4*)(g_Vl16 + g);
            }
        }

        // ---- scores: 1-product fp16 QK ----
        float sacc[8][4];
#pragma unroll
        for (int j = 0; j < 8; j++)
#pragma unroll
            for (int q = 0; q < 4; q++) sacc[j][q] = 0.f;

#pragma unroll
        for (int ks = 0; ks < 4; ks++) {
#pragma unroll
            for (int np = 0; np < 4; np++) {
                uint32_t off = (uint32_t)((np * 16 + bRow) * 128) +
                               (((uint32_t)(ks * 32 + bKb)) ^ bSw);
                uint32_t kh4[4];
                ldmx4(kh4, sb + OFF_K + off);
                mma_f16(sacc[2*np],   qh[ks], kh4);
                mma_f16(sacc[2*np+1], qh[ks], kh4 + 2);
            }
        }

        // ---- mask + scale ----
        if (need_mask) {
#pragma unroll
            for (int j = 0; j < 8; j++) {
                int kg = k0 + 8 * j + ((lane & 3) << 1);
                sacc[j][0] = (kg   <= qg0 && kg   + WIN > qg0) ? sacc[j][0] * sc : -1e30f;
                sacc[j][1] = (kg+1 <= qg0 && kg+1 + WIN > qg0) ? sacc[j][1] * sc : -1e30f;
                sacc[j][2] = (kg   <= qg1 && kg   + WIN > qg1) ? sacc[j][2] * sc : -1e30f;
                sacc[j][3] = (kg+1 <= qg1 && kg+1 + WIN > qg1) ? sacc[j][3] * sc : -1e30f;
            }
        } else {
#pragma unroll
            for (int j = 0; j < 8; j++) {
                sacc[j][0] *= sc; sacc[j][1] *= sc;
                sacc[j][2] *= sc; sacc[j][3] *= sc;
            }
        }

        // ---- online softmax ----
        float t0 = -1e30f, t1 = -1e30f;
#pragma unroll
        for (int j = 0; j < 8; j++) {
            t0 = fmaxf(t0, fmaxf(sacc[j][0], sacc[j][1]));
            t1 = fmaxf(t1, fmaxf(sacc[j][2], sacc[j][3]));
        }
        t0 = fmaxf(t0, __shfl_xor_sync(0xffffffffu, t0, 1));
        t0 = fmaxf(t0, __shfl_xor_sync(0xffffffffu, t0, 2));
        t1 = fmaxf(t1, __shfl_xor_sync(0xffffffffu, t1, 1));
        t1 = fmaxf(t1, __shfl_xor_sync(0xffffffffu, t1, 2));
        float mn0 = fmaxf(m0, t0), mn1 = fmaxf(m1, t1);
        float c0 = exp2f_fast(m0 - mn0), c1 = exp2f_fast(m1 - mn1);
        m0 = mn0; m1 = mn1;

        float s0 = 0.f, s1 = 0.f;
#pragma unroll
        for (int j = 0; j < 8; j++) {
            float p0 = exp2f_fast(sacc[j][0] - m0);
            float p1 = exp2f_fast(sacc[j][1] - m0);
            float p2 = exp2f_fast(sacc[j][2] - m1);
            float p3 = exp2f_fast(sacc[j][3] - m1);
            sacc[j][0] = p0; sacc[j][1] = p1; sacc[j][2] = p2; sacc[j][3] = p3;
            s0 += p0 + p1; s1 += p2 + p3;
        }
        s0 += __shfl_xor_sync(0xffffffffu, s0, 1);
        s0 += __shfl_xor_sync(0xffffffffu, s0, 2);
        s1 += __shfl_xor_sync(0xffffffffu, s1, 1);
        s1 += __shfl_xor_sync(0xffffffffu, s1, 2);
        l0 = l0 * c0 + s0;
        l1 = l1 * c1 + s1;
#pragma unroll
        for (int j = 0; j < 8; j++) {
            oacc[j][0] *= c0; oacc[j][1] *= c0;
            oacc[j][2] *= c1; oacc[j][3] *= c1;
        }

        // ---- pack P (fp16 hi/lo) ----
        uint32_t aPh[4][4], aPl[4][4];
#pragma unroll
        for (int t = 0; t < 4; t++) {
            pack_split2h(sacc[2*t][0],   sacc[2*t][1],   aPh[t][0], aPl[t][0]);
            pack_split2h(sacc[2*t][2],   sacc[2*t][3],   aPh[t][1], aPl[t][1]);
            pack_split2h(sacc[2*t+1][0], sacc[2*t+1][1], aPh[t][2], aPl[t][2]);
            pack_split2h(sacc[2*t+1][2], sacc[2*t+1][3], aPh[t][3], aPl[t][3]);
        }

        // ---- O += P V (3-product fp16) ----
#pragma unroll
        for (int t = 0; t < 4; t++) {
#pragma unroll
            for (int j2 = 0; j2 < 4; j2++) {
                uint32_t off = (uint32_t)((t * 16 + vRow) * 128) +
                               (((uint32_t)(j2 * 32 + vCb)) ^ vSw);
                uint32_t vh4[4], vl4[4];
                ldmx4t(vh4, sb + OFF_VH + off);
                ldmx4t(vl4, sb + OFF_VL + off);
                mma_f16(oacc[2*j2],   aPh[t], vh4);
                mma_f16(oacc[2*j2],   aPh[t], vl4);
                mma_f16(oacc[2*j2],   aPl[t], vh4);
                mma_f16(oacc[2*j2+1], aPh[t], vh4 + 2);
                mma_f16(oacc[2*j2+1], aPh[t], vl4 + 2);
                mma_f16(oacc[2*j2+1], aPl[t], vh4 + 2);
            }
        }

        __syncthreads();
        if (kt < kt_end) {
#pragma unroll
            for (int i = 0; i < 2; i++) {
                int idx = tid * 2 + i;
                int row = idx >> 3;
                int c16 = idx & 7;
                uint32_t off = SMEM_SWIZZLE_128B((uint32_t)(row * 128 + c16 * 16));
                *(uint4*)(smem + OFF_K  + off) = rk[i];
                *(uint4*)(smem + OFF_VH + off) = rvh[i];
                *(uint4*)(smem + OFF_VL + off) = rvl[i];
            }
            __syncthreads();
        }
    }

    // ---- epilogue: O /= l ----
    float inv0 = 1.f / l0, inv1 = 1.f / l1;
    const int r0g = q0 + w * 16 + (lane >> 2);
#pragma unroll
    for (int j = 0; j < 8; j++) {
        int c0 = h * HD + 8 * j + ((lane & 3) << 1);
        *(float2*)(g_O + (size_t)r0g * DIM + c0) =
            make_float2(oacc[j][0] * inv0, oacc[j][1] * inv0);
        *(float2*)(g_O + (size_t)(r0g + 8) * DIM + c0) =
            make_float2(oacc[j][2] * inv1, oacc[j][3] * inv1);
    }
}

// ---------------------------------------------------------------------------
extern "C" void kernel_launch(void* const* d_in, const int* in_sizes, int n_in,
                              void* d_out, int out_size)
{
    const float* x  = (const float*)d_in[0];
    const float* Wq = (const float*)d_in[1];
    const float* Wk = (const float*)d_in[2];
    const float* Wv = (const float*)d_in[3];
    const float* Wo = (const float*)d_in[4];
    float* out = (float*)d_out;
    (void)in_sizes; (void)n_in; (void)out_size;

    static float *pQ = nullptr, *pK = nullptr, *pV = nullptr, *pO = nullptr;
    static __half *pWh, *pWl;
    if (!pQ) {
        cudaGetSymbolAddress((void**)&pQ,  g_Q);
        cudaGetSymbolAddress((void**)&pK,  g_K);
        cudaGetSymbolAddress((void**)&pV,  g_V);
        cudaGetSymbolAddress((void**)&pO,  g_O);
        cudaGetSymbolAddress((void**)&pWh, g_Wh);
        cudaGetSymbolAddress((void**)&pWl, g_Wl);
        cudaFuncSetAttribute(gemm_f16<1>, cudaFuncAttributeMaxDynamicSharedMemorySize,
                             GSMEM_TOTAL);
        cudaFuncSetAttribute(gemm_f16<2>, cudaFuncAttributeMaxDynamicSharedMemorySize,
                             GSMEM_TOTAL);
        cudaFuncSetAttribute(gemm_f16<3>, cudaFuncAttributeMaxDynamicSharedMemorySize,
                             GSMEM_TOTAL);
        cudaFuncSetAttribute(swa_mma, cudaFuncAttributeMaxDynamicSharedMemorySize,
                             ASMEM_TOTAL);
    }

    split_all<<<(4 * NW / 2) / 256, 256>>>(Wq, Wk, Wv, Wo);

    dim3 gg(DIM / 128, S_LEN / 128);   // (8, 64)
    gemm_f16<1><<<gg, 256, GSMEM_TOTAL>>>(x, pWh + 0 * NW, pWl + 0 * NW, pQ);
    gemm_f16<1><<<gg, 256, GSMEM_TOTAL>>>(x, pWh + 1 * NW, pWl + 1 * NW, pK);
    gemm_f16<2><<<gg, 256, GSMEM_TOTAL>>>(x, pWh + 2 * NW, pWl + 2 * NW, pV);

    rope_split<<<(S_LEN * (DIM / 2)) / 256, 256>>>();

    swa_mma<<<dim3(S_LEN / 128, NH), 256, ASMEM_TOTAL>>>();

    gemm_f16<3><<<gg, 256, GSMEM_TOTAL>>>(pO, pWh + 3 * NW, pWl + 3 * NW, out);
}